// round 2
// baseline (speedup 1.0000x reference)
#include <cuda_runtime.h>
#include <stdint.h>
#include <math.h>

#define T_LEN 2048
#define ELMO  1024
#define SP_EMB 64
#define HDIM  1024
#define IN0   1088
#define TAGS  50
#define G4    4096
#define JCAP  14
#define CTAS_PER_DIR 74
#define REC_GRID (2 * CTAS_PER_DIR)
#define REC_THREADS 256

// smem: weights 4*JCAP*1024 floats + sg (4*JCAP) + sc (JCAP)
#define REC_SMEM_FLOATS (4 * JCAP * HDIM + 4 * JCAP + JCAP)
#define REC_SMEM_BYTES (REC_SMEM_FLOATS * 4)

// ---------------- scratch (static device globals; no allocation) -------------
__device__ float g_embeds[(size_t)T_LEN * IN0];        // 8.9 MB
__device__ float g_xproj[(size_t)T_LEN * 8192];        // 64 MB  (both dirs, [T][8192])
__device__ float g_h0[(size_t)T_LEN * 2048];           // 16 MB
__device__ float g_h1[(size_t)T_LEN * 2048];           // 16 MB
__device__ float g_bias[8192];
__device__ float g_hbuf[2 * 2 * HDIM];                 // [phase][dir][1024] (permuted)
__device__ unsigned g_bar[2];

// ---------------- helpers ----------------------------------------------------
__device__ __forceinline__ void fma2(unsigned long long &c, unsigned long long a,
                                     unsigned long long b) {
    asm("fma.rn.f32x2 %0, %1, %2, %3;" : "=l"(c) : "l"(a), "l"(b), "l"(c));
}
__device__ __forceinline__ unsigned long long pack2(float x) {
    unsigned long long r;
    unsigned u = __float_as_uint(x);
    asm("mov.b64 %0, {%1, %1};" : "=l"(r) : "r"(u));
    return r;
}
__device__ __forceinline__ float sigf(float x) { return 1.0f / (1.0f + expf(-x)); }

// ---------------- tiny kernels ------------------------------------------------
__global__ void embed_kernel(const float* __restrict__ sent,
                             const int* __restrict__ tags,
                             const float* __restrict__ emb) {
    int t = blockIdx.x;
    float* dst = g_embeds + (size_t)t * IN0;
    const float* s = sent + (size_t)t * ELMO;
    for (int i = threadIdx.x; i < ELMO; i += blockDim.x) dst[i] = s[i];
    const float* e = emb + (size_t)tags[t] * SP_EMB;
    for (int i = threadIdx.x; i < SP_EMB; i += blockDim.x) dst[ELMO + i] = e[i];
}

__global__ void bias_kernel(const float* __restrict__ b_ih,
                            const float* __restrict__ b_hh) {
    int i = blockIdx.x * blockDim.x + threadIdx.x;
    if (i < 8192) g_bias[i] = b_ih[i] + b_hh[i];
}

__global__ void init_kernel() {
    int i = blockIdx.x * blockDim.x + threadIdx.x;
    if (i < 2 * 2 * HDIM) g_hbuf[i] = 0.0f;
    if (i < 2) g_bar[i] = 0u;
}

// ---------------- SGEMM (NT): C[m][n] = sum_k A[m][k]*B[n][k] + bias[n] -------
// 128x128 tile, BK=8, 256 threads, 8x8 per thread, f32x2 packed FMA.
// Assumes M % 128 == 0, K % 8 == 0. N is guarded.
__global__ void __launch_bounds__(256, 2)
sgemm_nt(const float* __restrict__ A, const float* __restrict__ B,
         const float* __restrict__ bias, float* __restrict__ C,
         int M, int N, int K) {
    __shared__ float As[2][8][128];
    __shared__ float Bs[2][8][128];

    int tid = threadIdx.x;
    int bm = blockIdx.y * 128;
    int bn = blockIdx.x * 128;
    int lm = tid >> 1;            // 0..127 tile row for loads
    int lk = (tid & 1) * 4;       // 0 or 4
    int ty = tid >> 4;            // 0..15
    int tx = tid & 15;            // 0..15

    const float* Aptr = A + (size_t)(bm + lm) * K + lk;
    const float* Bptr = B + (size_t)(bn + lm) * K + lk;
    bool bvalid = (bn + lm) < N;

    float4 ra = *(const float4*)Aptr;
    float4 rb = bvalid ? *(const float4*)Bptr : make_float4(0.f, 0.f, 0.f, 0.f);
    As[0][lk + 0][lm] = ra.x; As[0][lk + 1][lm] = ra.y;
    As[0][lk + 2][lm] = ra.z; As[0][lk + 3][lm] = ra.w;
    Bs[0][lk + 0][lm] = rb.x; Bs[0][lk + 1][lm] = rb.y;
    Bs[0][lk + 2][lm] = rb.z; Bs[0][lk + 3][lm] = rb.w;
    __syncthreads();

    unsigned long long acc[8][4];
#pragma unroll
    for (int i = 0; i < 8; i++)
#pragma unroll
        for (int j = 0; j < 4; j++) acc[i][j] = 0ull;

    int nk = K >> 3;
    for (int kt = 0; kt < nk; kt++) {
        int buf = kt & 1;
        if (kt + 1 < nk) {
            ra = *(const float4*)(Aptr + (size_t)(kt + 1) * 8);
            rb = bvalid ? *(const float4*)(Bptr + (size_t)(kt + 1) * 8)
                        : make_float4(0.f, 0.f, 0.f, 0.f);
        }
#pragma unroll
        for (int kk = 0; kk < 8; kk++) {
            float4 a0 = *(const float4*)&As[buf][kk][ty * 8];
            float4 a1 = *(const float4*)&As[buf][kk][ty * 8 + 4];
            const unsigned long long* bp =
                (const unsigned long long*)&Bs[buf][kk][tx * 8];
            unsigned long long b0 = bp[0], b1 = bp[1], b2 = bp[2], b3 = bp[3];
            float av[8] = {a0.x, a0.y, a0.z, a0.w, a1.x, a1.y, a1.z, a1.w};
#pragma unroll
            for (int i = 0; i < 8; i++) {
                unsigned long long a2 = pack2(av[i]);
                fma2(acc[i][0], a2, b0);
                fma2(acc[i][1], a2, b1);
                fma2(acc[i][2], a2, b2);
                fma2(acc[i][3], a2, b3);
            }
        }
        if (kt + 1 < nk) {
            int nb = buf ^ 1;
            As[nb][lk + 0][lm] = ra.x; As[nb][lk + 1][lm] = ra.y;
            As[nb][lk + 2][lm] = ra.z; As[nb][lk + 3][lm] = ra.w;
            Bs[nb][lk + 0][lm] = rb.x; Bs[nb][lk + 1][lm] = rb.y;
            Bs[nb][lk + 2][lm] = rb.z; Bs[nb][lk + 3][lm] = rb.w;
            __syncthreads();
        }
    }

#pragma unroll
    for (int i = 0; i < 8; i++) {
        int m = bm + ty * 8 + i;
        float* crow = C + (size_t)m * N;
#pragma unroll
        for (int j2 = 0; j2 < 4; j2++) {
            int n0 = bn + tx * 8 + j2 * 2;
            unsigned long long v = acc[i][j2];
            float lo = __uint_as_float((unsigned)v);
            float hi = __uint_as_float((unsigned)(v >> 32));
            if (n0 < N)     crow[n0]     = lo + bias[n0];
            if (n0 + 1 < N) crow[n0 + 1] = hi + bias[n0 + 1];
        }
    }
}

// ---------------- persistent BiLSTM recurrence --------------------------------
// grid = 148 CTAs; CTA c: dir = c/74, owns h-indices [jbase, jbase+J).
// Weights (4 gates x J rows x 1024) live in SMEM for the whole kernel.
// h is published in a permuted layout: h_perm[(k%32)*32 + k/32] = h[k],
// so lane L needs exactly h_perm[L*32 .. L*32+31] (8x LDG.128).
__global__ void __launch_bounds__(REC_THREADS, 1)
lstm_rec(const float* __restrict__ w_hh,   // [2][4096][1024]
         const float* __restrict__ xproj,  // [T][8192], dir offset 4096
         float* __restrict__ hout)         // [T][2048]
{
    extern __shared__ float smem[];
    float* sw = smem;                          // 4*JCAP*1024
    float* sg = smem + 4 * JCAP * HDIM;        // 4*JCAP gate values
    float* sc = sg + 4 * JCAP;                 // JCAP cell states

    int cta  = blockIdx.x;
    int dir  = cta / CTAS_PER_DIR;
    int cidx = cta % CTAS_PER_DIR;
    int jbase = cidx * JCAP;
    int J = min(JCAP, HDIM - jbase);
    int tid = threadIdx.x;
    int warp = tid >> 5, lane = tid & 31;

    // Load this CTA's weight rows into SMEM (local row r = g*J + jj).
    for (int g = 0; g < 4; g++)
        for (int jj = 0; jj < J; jj++) {
            const float4* src = (const float4*)(w_hh +
                ((size_t)dir * G4 + (size_t)g * HDIM + jbase + jj) * HDIM);
            float4* dst = (float4*)(sw + (size_t)(g * J + jj) * HDIM);
            dst[tid] = src[tid];   // 256 threads x float4 = 1024 floats
        }
    if (tid < J) sc[tid] = 0.0f;
    __syncthreads();

    unsigned* bar = &g_bar[dir];

    for (int s = 0; s < T_LEN; s++) {
        int p = s & 1;
        const float* hsrc = g_hbuf + (size_t)(p * 2 + dir) * HDIM;

        // hreg[m] = h[lane + 32*m] via permuted contiguous load
        float hreg[32];
        {
            const float4* hp = (const float4*)(hsrc + lane * 32);
#pragma unroll
            for (int q = 0; q < 8; q++) {
                float4 v = hp[q];
                hreg[4 * q + 0] = v.x; hreg[4 * q + 1] = v.y;
                hreg[4 * q + 2] = v.z; hreg[4 * q + 3] = v.w;
            }
        }

        // 4*J dot products, one row per warp per pass, strided conflict-free LDS
        for (int r = warp; r < 4 * J; r += 8) {
            const float* wr = sw + (size_t)r * HDIM;
            float a0 = 0.f, a1 = 0.f, a2 = 0.f, a3 = 0.f;
#pragma unroll
            for (int m = 0; m < 32; m += 4) {
                a0 = fmaf(wr[lane + 32 * (m + 0)], hreg[m + 0], a0);
                a1 = fmaf(wr[lane + 32 * (m + 1)], hreg[m + 1], a1);
                a2 = fmaf(wr[lane + 32 * (m + 2)], hreg[m + 2], a2);
                a3 = fmaf(wr[lane + 32 * (m + 3)], hreg[m + 3], a3);
            }
            float acc = (a0 + a1) + (a2 + a3);
#pragma unroll
            for (int off = 16; off; off >>= 1)
                acc += __shfl_xor_sync(0xffffffffu, acc, off);
            if (lane == 0) sg[r] = acc;
        }
        __syncthreads();

        if (tid < J) {
            int t_in = dir ? (T_LEN - 1 - s) : s;
            const float* xp = xproj + (size_t)t_in * 8192 + dir * G4;
            int j = jbase + tid;
            float gi = sg[0 * J + tid] + xp[j];
            float gf = sg[1 * J + tid] + xp[HDIM + j];
            float gg = sg[2 * J + tid] + xp[2 * HDIM + j];
            float go = sg[3 * J + tid] + xp[3 * HDIM + j];
            float c  = sigf(gf) * sc[tid] + sigf(gi) * tanhf(gg);
            float hv = sigf(go) * tanhf(c);
            sc[tid] = c;
            // publish permuted h for next step
            g_hbuf[(size_t)((p ^ 1) * 2 + dir) * HDIM + (j & 31) * 32 + (j >> 5)] = hv;
            hout[(size_t)t_in * 2048 + dir * HDIM + j] = hv;
        }
        __threadfence();
        __syncthreads();

        if (tid == 0) {
            atomicAdd(bar, 1u);
            unsigned target = (unsigned)(s + 1) * CTAS_PER_DIR;
            unsigned v;
            do {
                asm volatile("ld.global.acquire.gpu.u32 %0, [%1];"
                             : "=r"(v) : "l"(bar));
            } while (v < target);
        }
        __syncthreads();
    }
}

// ---------------- launcher ----------------------------------------------------
extern "C" void kernel_launch(void* const* d_in, const int* in_sizes, int n_in,
                              void* d_out, int out_size) {
    const float* sentence = (const float*)d_in[0];
    const int*   tags     = (const int*)d_in[1];
    const float* emb      = (const float*)d_in[2];
    const float* w_ih0    = (const float*)d_in[3];
    const float* w_hh0    = (const float*)d_in[4];
    const float* b_ih0    = (const float*)d_in[5];
    const float* b_hh0    = (const float*)d_in[6];
    const float* w_ih1    = (const float*)d_in[7];
    const float* w_hh1    = (const float*)d_in[8];
    const float* b_ih1    = (const float*)d_in[9];
    const float* b_hh1    = (const float*)d_in[10];
    const float* w_out    = (const float*)d_in[11];
    const float* b_out    = (const float*)d_in[12];
    float* out = (float*)d_out;

    cudaFuncSetAttribute(lstm_rec, cudaFuncAttributeMaxDynamicSharedMemorySize,
                         REC_SMEM_BYTES);

    float *p_embeds, *p_xproj, *p_h0, *p_h1, *p_bias;
    cudaGetSymbolAddress((void**)&p_embeds, g_embeds);
    cudaGetSymbolAddress((void**)&p_xproj,  g_xproj);
    cudaGetSymbolAddress((void**)&p_h0,     g_h0);
    cudaGetSymbolAddress((void**)&p_h1,     g_h1);
    cudaGetSymbolAddress((void**)&p_bias,   g_bias);

    // embeds
    embed_kernel<<<T_LEN, 128>>>(sentence, tags, emb);

    // ---- layer 0 ----
    bias_kernel<<<32, 256>>>(b_ih0, b_hh0);
    sgemm_nt<<<dim3(8192 / 128, T_LEN / 128), 256>>>(
        p_embeds, w_ih0, p_bias, p_xproj, T_LEN, 8192, IN0);
    init_kernel<<<16, 256>>>();
    lstm_rec<<<REC_GRID, REC_THREADS, REC_SMEM_BYTES>>>(w_hh0, p_xproj, p_h0);

    // ---- layer 1 ----
    bias_kernel<<<32, 256>>>(b_ih1, b_hh1);
    sgemm_nt<<<dim3(8192 / 128, T_LEN / 128), 256>>>(
        p_h0, w_ih1, p_bias, p_xproj, T_LEN, 8192, 2048);
    init_kernel<<<16, 256>>>();
    lstm_rec<<<REC_GRID, REC_THREADS, REC_SMEM_BYTES>>>(w_hh1, p_xproj, p_h1);

    // ---- output projection ----
    sgemm_nt<<<dim3(1, T_LEN / 128), 256>>>(
        p_h1, w_out, b_out, out, T_LEN, TAGS, 2048);
}

// round 4
// speedup vs baseline: 1.6361x; 1.6361x over previous
#include <cuda_runtime.h>
#include <stdint.h>
#include <math.h>

#define T_LEN 2048
#define ELMO  1024
#define SP_EMB 64
#define HDIM  1024
#define IN0   1088
#define TAGS  50
#define G4    4096
#define JCAP  14
#define CTAS_PER_DIR 74
#define REC_GRID (2 * CTAS_PER_DIR)
#define REC_THREADS 256

#define NREG_P   4                 // rows-per-warp cached in registers (p=0..3)
#define SMEM_ROWS 24               // rows 32..55 live in SMEM (p=4..6)
// smem: sw 24*1024 f32 + sxp[56] + sg[56] + sc[16]
#define REC_SMEM_FLOATS (SMEM_ROWS * HDIM + 56 + 56 + 16)
#define REC_SMEM_BYTES (REC_SMEM_FLOATS * 4)

// ---------------- scratch (static device globals; no allocation) -------------
__device__ float g_embeds[(size_t)T_LEN * IN0];
__device__ float g_xproj[(size_t)T_LEN * 8192];
__device__ float g_h0[(size_t)T_LEN * 2048];
__device__ float g_h1[(size_t)T_LEN * 2048];
__device__ float g_bias[2][8192];
__device__ float g_hb[2][2][2][HDIM];     // [layer][phase][dir][H]
__device__ unsigned g_barc[2][2];         // [layer][dir]
__device__ int g_dummy;

// ---------------- helpers ----------------------------------------------------
__device__ __forceinline__ void fma2(unsigned long long &c, unsigned long long a,
                                     unsigned long long b) {
    asm("fma.rn.f32x2 %0, %1, %2, %3;" : "=l"(c) : "l"(a), "l"(b), "l"(c));
}
__device__ __forceinline__ unsigned long long pack2(float x) {
    unsigned long long r;
    unsigned u = __float_as_uint(x);
    asm("mov.b64 %0, {%1, %1};" : "=l"(r) : "r"(u));
    return r;
}
__device__ __forceinline__ float lo32(unsigned long long v) {
    return __uint_as_float((unsigned)v);
}
__device__ __forceinline__ float hi32(unsigned long long v) {
    return __uint_as_float((unsigned)(v >> 32));
}
__device__ __forceinline__ float sigf(float x) {
    return 1.0f / (1.0f + __expf(-x));
}
__device__ __forceinline__ float tanhfast(float x) {
    float xc = fminf(fmaxf(x, -15.0f), 15.0f);
    float e = __expf(-2.0f * xc);
    return (1.0f - e) / (1.0f + e);
}

// ---------------- tiny kernels ------------------------------------------------
__global__ void embed_kernel(const float* __restrict__ sent,
                             const int* __restrict__ tags,
                             const float* __restrict__ emb) {
    int t = blockIdx.x;
    float* dst = g_embeds + (size_t)t * IN0;
    const float* s = sent + (size_t)t * ELMO;
    for (int i = threadIdx.x; i < ELMO; i += blockDim.x) dst[i] = s[i];
    const float* e = emb + (size_t)tags[t] * SP_EMB;
    for (int i = threadIdx.x; i < SP_EMB; i += blockDim.x) dst[ELMO + i] = e[i];
}

__global__ void bias_kernel(const float* __restrict__ bi0, const float* __restrict__ bh0,
                            const float* __restrict__ bi1, const float* __restrict__ bh1) {
    int i = blockIdx.x * blockDim.x + threadIdx.x;
    if (i < 8192) {
        g_bias[0][i] = bi0[i] + bh0[i];
        g_bias[1][i] = bi1[i] + bh1[i];
    }
}

__global__ void init_kernel() {
    int i = blockIdx.x * blockDim.x + threadIdx.x;
    if (i < 2 * 2 * 2 * HDIM) ((float*)g_hb)[i] = 0.0f;
    if (i < 4) ((unsigned*)g_barc)[i] = 0u;
}

__global__ void pad_kernel() {
    if (threadIdx.x == 0) g_dummy = 1;   // trivial; exists to align ncu's -s 5
}

// ---------------- SGEMM (NT): C[m][n] = sum_k A[m][k]*B[n][k] + bias[n] -------
__global__ void __launch_bounds__(256, 2)
sgemm_nt(const float* __restrict__ A, const float* __restrict__ B,
         const float* __restrict__ bias, float* __restrict__ C,
         int M, int N, int K) {
    __shared__ float As[2][8][128];
    __shared__ float Bs[2][8][128];

    int tid = threadIdx.x;
    int bm = blockIdx.y * 128;
    int bn = blockIdx.x * 128;
    int lm = tid >> 1;
    int lk = (tid & 1) * 4;
    int ty = tid >> 4;
    int tx = tid & 15;

    const float* Aptr = A + (size_t)(bm + lm) * K + lk;
    const float* Bptr = B + (size_t)(bn + lm) * K + lk;
    bool bvalid = (bn + lm) < N;

    float4 ra = *(const float4*)Aptr;
    float4 rb = bvalid ? *(const float4*)Bptr : make_float4(0.f, 0.f, 0.f, 0.f);
    As[0][lk + 0][lm] = ra.x; As[0][lk + 1][lm] = ra.y;
    As[0][lk + 2][lm] = ra.z; As[0][lk + 3][lm] = ra.w;
    Bs[0][lk + 0][lm] = rb.x; Bs[0][lk + 1][lm] = rb.y;
    Bs[0][lk + 2][lm] = rb.z; Bs[0][lk + 3][lm] = rb.w;
    __syncthreads();

    unsigned long long acc[8][4];
#pragma unroll
    for (int i = 0; i < 8; i++)
#pragma unroll
        for (int j = 0; j < 4; j++) acc[i][j] = 0ull;

    int nk = K >> 3;
    for (int kt = 0; kt < nk; kt++) {
        int buf = kt & 1;
        if (kt + 1 < nk) {
            ra = *(const float4*)(Aptr + (size_t)(kt + 1) * 8);
            rb = bvalid ? *(const float4*)(Bptr + (size_t)(kt + 1) * 8)
                        : make_float4(0.f, 0.f, 0.f, 0.f);
        }
#pragma unroll
        for (int kk = 0; kk < 8; kk++) {
            float4 a0 = *(const float4*)&As[buf][kk][ty * 8];
            float4 a1 = *(const float4*)&As[buf][kk][ty * 8 + 4];
            const unsigned long long* bp =
                (const unsigned long long*)&Bs[buf][kk][tx * 8];
            unsigned long long b0 = bp[0], b1 = bp[1], b2 = bp[2], b3 = bp[3];
            float av[8] = {a0.x, a0.y, a0.z, a0.w, a1.x, a1.y, a1.z, a1.w};
#pragma unroll
            for (int i = 0; i < 8; i++) {
                unsigned long long a2 = pack2(av[i]);
                fma2(acc[i][0], a2, b0);
                fma2(acc[i][1], a2, b1);
                fma2(acc[i][2], a2, b2);
                fma2(acc[i][3], a2, b3);
            }
        }
        if (kt + 1 < nk) {
            int nb = buf ^ 1;
            As[nb][lk + 0][lm] = ra.x; As[nb][lk + 1][lm] = ra.y;
            As[nb][lk + 2][lm] = ra.z; As[nb][lk + 3][lm] = ra.w;
            Bs[nb][lk + 0][lm] = rb.x; Bs[nb][lk + 1][lm] = rb.y;
            Bs[nb][lk + 2][lm] = rb.z; Bs[nb][lk + 3][lm] = rb.w;
            __syncthreads();
        }
    }

#pragma unroll
    for (int i = 0; i < 8; i++) {
        int m = bm + ty * 8 + i;
        float* crow = C + (size_t)m * N;
#pragma unroll
        for (int j2 = 0; j2 < 4; j2++) {
            int n0 = bn + tx * 8 + j2 * 2;
            unsigned long long v = acc[i][j2];
            if (n0 < N)     crow[n0]     = lo32(v) + bias[n0];
            if (n0 + 1 < N) crow[n0 + 1] = hi32(v) + bias[n0 + 1];
        }
    }
}

// ---------------- persistent BiLSTM recurrence --------------------------------
// 148 CTAs (74/dir, 1/SM). CTA owns J=14 hidden units -> 56 gate rows.
// Per warp: 7 rows (r = warp + 8p). p=0..3 weights live in REGISTERS
// (64 x f32x2 per thread), p=4..6 in SMEM. All dots via fma.rn.f32x2.
// h double-buffered in global; k-pairs load as u64 (naturally packed f32x2).
__global__ void __launch_bounds__(REC_THREADS, 1)
lstm_rec(const float* __restrict__ w_hh,   // [2][4096][1024]
         const float* __restrict__ xproj,  // [T][8192]
         float* __restrict__ hout,         // [T][2048]
         float* __restrict__ hbuf,         // [2][2][1024] this layer
         unsigned* __restrict__ barc)      // [2] this layer
{
    extern __shared__ float smem[];
    float* sw  = smem;                          // SMEM_ROWS * 1024
    float* sxp = smem + SMEM_ROWS * HDIM;       // 56
    float* sg  = sxp + 56;                      // 56
    float* sc  = sg + 56;                       // 16

    int cta  = blockIdx.x;
    int dir  = cta / CTAS_PER_DIR;
    int cidx = cta % CTAS_PER_DIR;
    int jbase = cidx * JCAP;
    int J = min(JCAP, HDIM - jbase);
    int R = 4 * J;
    int tid = threadIdx.x;
    int warp = tid >> 5, lane = tid & 31;
    int gate4 = (tid < R) ? tid / J : 0;
    int jj    = (tid < R) ? tid % J : 0;

    // ---- load register-resident weight rows (p = 0..3) ----
    unsigned long long wreg[NREG_P][16];
#pragma unroll
    for (int p = 0; p < NREG_P; p++) {
        int r = warp + 8 * p;
        if (r < R) {
            int g = r / J, j2 = r % J;
            const unsigned long long* src = (const unsigned long long*)(w_hh +
                ((size_t)dir * G4 + (size_t)g * HDIM + jbase + j2) * HDIM);
#pragma unroll
            for (int m = 0; m < 16; m++) wreg[p][m] = src[lane + 32 * m];
        } else {
#pragma unroll
            for (int m = 0; m < 16; m++) wreg[p][m] = 0ull;
        }
    }
    // ---- load SMEM weight rows (p = 4..6 -> rows 32..55) ----
    for (int rr = 0; rr < SMEM_ROWS; rr++) {
        int r = 32 + rr;
        if (r >= R) break;
        int g = r / J, j2 = r % J;
        const float4* src = (const float4*)(w_hh +
            ((size_t)dir * G4 + (size_t)g * HDIM + jbase + j2) * HDIM);
        ((float4*)(sw + (size_t)rr * HDIM))[tid] = src[tid];
    }
    if (tid < J) sc[tid] = 0.0f;
    __syncthreads();

    unsigned* bar = &barc[dir];

    for (int s = 0; s < T_LEN; s++) {
        int p = s & 1;
        int t_in = dir ? (T_LEN - 1 - s) : s;

        // h pairs: lane L needs pairs {L+32m}, stored naturally as float2
        const unsigned long long* hp = (const unsigned long long*)
            (hbuf + (size_t)(p * 2 + dir) * HDIM);
        unsigned long long hu[16];
#pragma unroll
        for (int m = 0; m < 16; m++) hu[m] = hp[lane + 32 * m];

        // prefetch x-projection for this step (hidden under the dots)
        float xpv = 0.0f;
        if (tid < R)
            xpv = xproj[(size_t)t_in * 8192 + dir * G4 + gate4 * HDIM + jbase + jj];

        // ---- dot products: 4 register rows + 3 smem rows ----
        float rsum[7];
#pragma unroll
        for (int q = 0; q < NREG_P; q++) {
            unsigned long long a = 0ull;
#pragma unroll
            for (int m = 0; m < 16; m++) fma2(a, wreg[q][m], hu[m]);
            rsum[q] = lo32(a) + hi32(a);
        }
#pragma unroll
        for (int q = 0; q < 3; q++) {
            int rr = q * 8 + warp;                 // smem row id (global row 32+rr)
            unsigned long long a = 0ull;
            if (32 + rr < R) {
                const unsigned long long* wr =
                    (const unsigned long long*)(sw + (size_t)rr * HDIM);
#pragma unroll
                for (int m = 0; m < 16; m++) fma2(a, wr[lane + 32 * m], hu[m]);
            }
            rsum[NREG_P + q] = lo32(a) + hi32(a);
        }

        // ---- warp reductions ----
#pragma unroll
        for (int q = 0; q < 7; q++) {
            float v = rsum[q];
#pragma unroll
            for (int off = 16; off; off >>= 1)
                v += __shfl_xor_sync(0xffffffffu, v, off);
            int r = (q < NREG_P) ? (warp + 8 * q) : (32 + (q - NREG_P) * 8 + warp);
            if (lane == 0 && r < R) sg[r] = v;
        }
        if (tid < R) sxp[tid] = xpv;
        __syncthreads();

        // ---- gate math + publish h ----
        float hv_new = 0.0f;
        if (tid < J) {
            float gi = sg[0 * J + tid] + sxp[0 * J + tid];
            float gf = sg[1 * J + tid] + sxp[1 * J + tid];
            float gg = sg[2 * J + tid] + sxp[2 * J + tid];
            float go = sg[3 * J + tid] + sxp[3 * J + tid];
            float c  = sigf(gf) * sc[tid] + sigf(gi) * tanhfast(gg);
            hv_new   = sigf(go) * tanhfast(c);
            sc[tid]  = c;
            hbuf[(size_t)((p ^ 1) * 2 + dir) * HDIM + jbase + tid] = hv_new;
        }
        __syncthreads();

        // ---- inter-CTA barrier (release arrive + acquire spin) ----
        if (tid == 0) {
            asm volatile("red.release.gpu.global.add.u32 [%0], %1;"
                         :: "l"(bar), "r"(1u) : "memory");
        }
        if (tid < J)   // overlap with tid0's spin
            hout[(size_t)t_in * 2048 + dir * HDIM + jbase + tid] = hv_new;
        if (tid == 0) {
            unsigned target = (unsigned)(s + 1) * CTAS_PER_DIR;
            unsigned v;
            do {
                asm volatile("ld.global.acquire.gpu.u32 %0, [%1];"
                             : "=r"(v) : "l"(bar));
            } while (v < target);
        }
        __syncthreads();
    }
}

// ---------------- launcher ----------------------------------------------------
extern "C" void kernel_launch(void* const* d_in, const int* in_sizes, int n_in,
                              void* d_out, int out_size) {
    const float* sentence = (const float*)d_in[0];
    const int*   tags     = (const int*)d_in[1];
    const float* emb      = (const float*)d_in[2];
    const float* w_ih0    = (const float*)d_in[3];
    const float* w_hh0    = (const float*)d_in[4];
    const float* b_ih0    = (const float*)d_in[5];
    const float* b_hh0    = (const float*)d_in[6];
    const float* w_ih1    = (const float*)d_in[7];
    const float* w_hh1    = (const float*)d_in[8];
    const float* b_ih1    = (const float*)d_in[9];
    const float* b_hh1    = (const float*)d_in[10];
    const float* w_out    = (const float*)d_in[11];
    const float* b_out    = (const float*)d_in[12];
    float* out = (float*)d_out;

    cudaFuncSetAttribute(lstm_rec, cudaFuncAttributeMaxDynamicSharedMemorySize,
                         REC_SMEM_BYTES);

    float *p_embeds, *p_xproj, *p_h0, *p_h1, *p_bias, *p_hb;
    unsigned* p_bar;
    cudaGetSymbolAddress((void**)&p_embeds, g_embeds);
    cudaGetSymbolAddress((void**)&p_xproj,  g_xproj);
    cudaGetSymbolAddress((void**)&p_h0,     g_h0);
    cudaGetSymbolAddress((void**)&p_h1,     g_h1);
    cudaGetSymbolAddress((void**)&p_bias,   g_bias);
    cudaGetSymbolAddress((void**)&p_hb,     g_hb);
    cudaGetSymbolAddress((void**)&p_bar,    g_barc);

    // launch order tuned so ncu (-s 5 -c 1) captures lstm_rec (launch #6)
    embed_kernel<<<T_LEN, 128>>>(sentence, tags, emb);                       // 1
    bias_kernel<<<32, 256>>>(b_ih0, b_hh0, b_ih1, b_hh1);                    // 2
    init_kernel<<<32, 256>>>();                                              // 3
    pad_kernel<<<1, 32>>>();                                                 // 4

    sgemm_nt<<<dim3(64, 16), 256>>>(p_embeds, w_ih0, p_bias,                 // 5
                                    p_xproj, T_LEN, 8192, IN0);
    lstm_rec<<<REC_GRID, REC_THREADS, REC_SMEM_BYTES>>>(                     // 6
        w_hh0, p_xproj, p_h0, p_hb, p_bar);

    sgemm_nt<<<dim3(64, 16), 256>>>(p_h0, w_ih1, p_bias + 8192,              // 7
                                    p_xproj, T_LEN, 8192, 2048);
    lstm_rec<<<REC_GRID, REC_THREADS, REC_SMEM_BYTES>>>(                     // 8
        w_hh1, p_xproj, p_h1, p_hb + 2 * 2 * HDIM, p_bar + 2);

    sgemm_nt<<<dim3(1, 16), 256>>>(p_h1, w_out, b_out, out, T_LEN, TAGS, 2048); // 9
}